// round 6
// baseline (speedup 1.0000x reference)
#include <cuda_runtime.h>

// DWT Haar loss: pred/target [32,3,512,512] fp32.
// Linear DWT -> operate on diff. Per 2x2 block (a,b,c,d) of diff:
//   contribution = |a+b+c+d| + |a+b-c-d| + |a-b+c-d| + |a-b-c+d|
// loss = 0.5 * sum / N_blocks.
//
// Viewed as 24576 row-pairs of 512 floats (128 float4 per row).
// One work item = one float4 from row 2m + matching float4 from row 2m+1
// (both tensors) = two 2x2 blocks. Simple grid-stride (R1 body; the 2x
// strided unroll of R2 regressed DRAM utilization). Single kernel: last
// CTA finalizes the scalar via threadfence reduction (no memset node).

static constexpr int TOTAL_QUADS = 24576 * 128;       // 3,145,728
static constexpr float SCALE = 0.5f / 6291456.0f;     // 0.5 / N_blocks

__device__ float    g_scratch = 0.0f;
__device__ unsigned g_ctr     = 0u;

__global__ void __launch_bounds__(256) dwt_loss_kernel(
    const float4* __restrict__ pred,
    const float4* __restrict__ tgt,
    float* __restrict__ out)
{
    float acc = 0.0f;
    const int stride = gridDim.x * blockDim.x;
    for (int i = blockIdx.x * blockDim.x + threadIdx.x; i < TOTAL_QUADS; i += stride) {
        const int m = i >> 7;            // row-pair index
        const int q = i & 127;           // float4 index within row
        const int base0 = m * 256 + q;   // row 2m   (float4 units)
        const int base1 = base0 + 128;   // row 2m+1

        float4 p0 = pred[base0];
        float4 p1 = pred[base1];
        float4 t0 = tgt[base0];
        float4 t1 = tgt[base1];

        // Block 0: cols 4q, 4q+1
        {
            float a = p0.x - t0.x, b = p0.y - t0.y;
            float c = p1.x - t1.x, d = p1.y - t1.y;
            float apb = a + b, amb = a - b, cpd = c + d, cmd = c - d;
            acc += fabsf(apb + cpd) + fabsf(apb - cpd)
                 + fabsf(amb + cmd) + fabsf(amb - cmd);
        }
        // Block 1: cols 4q+2, 4q+3
        {
            float a = p0.z - t0.z, b = p0.w - t0.w;
            float c = p1.z - t1.z, d = p1.w - t1.w;
            float apb = a + b, amb = a - b, cpd = c + d, cmd = c - d;
            acc += fabsf(apb + cpd) + fabsf(apb - cpd)
                 + fabsf(amb + cmd) + fabsf(amb - cmd);
        }
    }

    // Warp reduction
    #pragma unroll
    for (int o = 16; o > 0; o >>= 1)
        acc += __shfl_xor_sync(0xffffffffu, acc, o);

    __shared__ float warp_sums[8];
    if ((threadIdx.x & 31) == 0)
        warp_sums[threadIdx.x >> 5] = acc;
    __syncthreads();

    if (threadIdx.x < 32) {
        float v = (threadIdx.x < 8) ? warp_sums[threadIdx.x] : 0.0f;
        #pragma unroll
        for (int o = 4; o > 0; o >>= 1)
            v += __shfl_xor_sync(0xffffffffu, v, o);

        if (threadIdx.x == 0) {
            atomicAdd(&g_scratch, v);
            __threadfence();
            unsigned old = atomicAdd(&g_ctr, 1u);
            if (old == gridDim.x - 1) {
                // Last CTA: finalize and reset state for next graph replay.
                float total = atomicAdd(&g_scratch, 0.0f);
                out[0] = total * SCALE;
                atomicExch(&g_scratch, 0.0f);
                atomicExch(&g_ctr, 0u);
            }
        }
    }
}

extern "C" void kernel_launch(void* const* d_in, const int* in_sizes, int n_in,
                              void* d_out, int out_size) {
    const float4* pred = (const float4*)d_in[0];
    const float4* tgt  = (const float4*)d_in[1];
    float* out = (float*)d_out;

    // 2 full waves: 148 SMs * 8 CTAs (256 thr, 32 regs) * 2.
    dwt_loss_kernel<<<2368, 256>>>(pred, tgt, out);
}

// round 7
// speedup vs baseline: 1.0216x; 1.0216x over previous
#include <cuda_runtime.h>

// DWT Haar loss: pred/target [32,3,512,512] fp32.
// Linear DWT -> operate on diff. Per 2x2 block (a,b,c,d) of diff:
//   contribution = |a+b+c+d| + |a+b-c-d| + |a-b+c-d| + |a-b-c+d|
// loss = 0.5 * sum / N_blocks.
//
// One-shot design: 24576 row-pairs x 512 floats. Work item = (row-pair m,
// quad q in [0,64)): thread loads float4 at columns q and q+64 from rows 2m
// and 2m+1, both tensors = 8 back-to-back LDG.128 (MLP_p1=8), computes 4
// Haar blocks, block-reduces, atomically accumulates. No loops, no tails.
// Last CTA finalizes the scalar (threadfence reduction) and resets state.

static constexpr int TOTAL_ITEMS = 24576 * 64;        // 1,572,864 threads
static constexpr float SCALE = 0.5f / 6291456.0f;     // 0.5 / N_blocks

__device__ float    g_scratch = 0.0f;
__device__ unsigned g_ctr     = 0u;

__device__ __forceinline__ float haar_quad(const float4& p0, const float4& p1,
                                           const float4& t0, const float4& t1)
{
    float acc;
    {
        float a = p0.x - t0.x, b = p0.y - t0.y;
        float c = p1.x - t1.x, d = p1.y - t1.y;
        float apb = a + b, amb = a - b, cpd = c + d, cmd = c - d;
        acc = fabsf(apb + cpd) + fabsf(apb - cpd)
            + fabsf(amb + cmd) + fabsf(amb - cmd);
    }
    {
        float a = p0.z - t0.z, b = p0.w - t0.w;
        float c = p1.z - t1.z, d = p1.w - t1.w;
        float apb = a + b, amb = a - b, cpd = c + d, cmd = c - d;
        acc += fabsf(apb + cpd) + fabsf(apb - cpd)
             + fabsf(amb + cmd) + fabsf(amb - cmd);
    }
    return acc;
}

__global__ void __launch_bounds__(256) dwt_loss_kernel(
    const float4* __restrict__ pred,
    const float4* __restrict__ tgt,
    float* __restrict__ out)
{
    const int i = blockIdx.x * 256 + threadIdx.x;   // grid sized exactly
    const int m = i >> 6;                           // row-pair index
    const int q = i & 63;                           // quad in first half-row
    const int b00 = m * 256 + q;                    // row 2m,   col quad q
    const int b01 = b00 + 64;                       // row 2m,   col quad q+64
    const int b10 = b00 + 128;                      // row 2m+1, col quad q
    const int b11 = b00 + 192;                      // row 2m+1, col quad q+64

    // 8 independent 16B loads, front-batched.
    float4 p00 = pred[b00];
    float4 p01 = pred[b01];
    float4 p10 = pred[b10];
    float4 p11 = pred[b11];
    float4 t00 = tgt[b00];
    float4 t01 = tgt[b01];
    float4 t10 = tgt[b10];
    float4 t11 = tgt[b11];

    float acc = haar_quad(p00, p10, t00, t10)
              + haar_quad(p01, p11, t01, t11);

    // Warp reduction
    #pragma unroll
    for (int o = 16; o > 0; o >>= 1)
        acc += __shfl_xor_sync(0xffffffffu, acc, o);

    __shared__ float warp_sums[8];
    if ((threadIdx.x & 31) == 0)
        warp_sums[threadIdx.x >> 5] = acc;
    __syncthreads();

    if (threadIdx.x < 32) {
        float v = (threadIdx.x < 8) ? warp_sums[threadIdx.x] : 0.0f;
        #pragma unroll
        for (int o = 4; o > 0; o >>= 1)
            v += __shfl_xor_sync(0xffffffffu, v, o);

        if (threadIdx.x == 0) {
            atomicAdd(&g_scratch, v);
            __threadfence();
            unsigned old = atomicAdd(&g_ctr, 1u);
            if (old == gridDim.x - 1) {
                // Last CTA: finalize and reset state for next graph replay.
                float total = atomicAdd(&g_scratch, 0.0f);
                out[0] = total * SCALE;
                atomicExch(&g_scratch, 0.0f);
                atomicExch(&g_ctr, 0u);
            }
        }
    }
}

extern "C" void kernel_launch(void* const* d_in, const int* in_sizes, int n_in,
                              void* d_out, int out_size) {
    const float4* pred = (const float4*)d_in[0];
    const float4* tgt  = (const float4*)d_in[1];
    float* out = (float*)d_out;

    dwt_loss_kernel<<<TOTAL_ITEMS / 256, 256>>>(pred, tgt, out);
}